// round 5
// baseline (speedup 1.0000x reference)
#include <cuda_runtime.h>

// XdGate on site INDEX=3 of an L=8 qutrit (D=3) state vector, N = 3^8 = 6561.
//
// U = I x I x I x M x I x I x I x I with M|i> = |(3-i) mod 3> — a pure
// permutation of the site-3 trit (stride 3^4 = 81):
//   t=0 -> delta 0, t=1 -> +81, t=2 -> -81 (element offsets).
//
// Launch-overhead bound: across 4 structural variants, ncu kernel time is
// 3.97-4.54us with issue <8% and DRAM 0.1% — fixed launch/ramp cost dominates,
// harness timing noise (+-0.5us) exceeds all body deltas. This is the
// measured-fastest body (R4: trit from threadIdx only, since blockDim=243 is
// a multiple of 3*STRIDE; exact 27x243 cover, no bounds guard), with unsigned
// index math so ptxas emits the leanest address sequence.

static constexpr unsigned STRIDE = 81u;   // 3^4

__global__ __launch_bounds__(243) void xd_gate_kernel(
    const float* __restrict__ x, float* __restrict__ out) {
    unsigned tid = threadIdx.x;                 // 0..242
    unsigned t = tid / STRIDE;                  // site-3 trit: 0,1,2
    int d = (int)(t == 1u) - (int)(t == 2u);    // 0 -> 0, 1 -> +1, 2 -> -1
    unsigned idx = blockIdx.x * 243u + tid;     // exact cover of [0, 6561)
    out[idx] = x[(int)idx + d * (int)STRIDE];
}

extern "C" void kernel_launch(void* const* d_in, const int* in_sizes, int n_in,
                              void* d_out, int out_size) {
    const float* x = (const float*)d_in[0];   // [6561, 1] float32
    // d_in[1] is M [3,3] — permutation baked in.
    float* out = (float*)d_out;

    xd_gate_kernel<<<27, 243>>>(x, out);      // 27 * 243 = 6561 exactly
}

// round 6
// speedup vs baseline: 1.0284x; 1.0284x over previous
#include <cuda_runtime.h>

// XdGate on site INDEX=3 of an L=8 qutrit (D=3) state vector, N = 3^8 = 6561.
//
// U = I x I x I x M x I x I x I x I with M|i> = |(3-i) mod 3> — a pure
// permutation of the site-3 trit (stride 3^4 = 81):
//   t=0 -> delta 0, t=1 -> +81, t=2 -> -81 (element offsets).
//
// FINAL (floor-confirmation of the best-measured variant, R3):
// Launch-overhead bound — across 5 structural variants (grids 7/26/27,
// scalar/vectorized, guard/no-guard), ncu kernel time stayed 3.97-4.54us
// with issue <=8% and DRAM 0.1%; harness graph-replay timing reproducibly
// ranks this body fastest (5.02us vs 5.79-6.08 for the others).
// Exact grid cover 27 x 243 = 6561 -> no bounds guard, no tail; branchless
// delta; one scalar gather per thread. Vectorized 16B access is impossible:
// src and dst offsets differ by 81 elements (4 bytes mod 16).

static constexpr int STRIDE = 81;   // 3^4

__global__ __launch_bounds__(243) void xd_gate_kernel(
    const float* __restrict__ x, float* __restrict__ out) {
    int idx = blockIdx.x * 243 + threadIdx.x;   // exact cover of [0, 6561)

    int t = (idx / STRIDE) % 3;
    // delta multiplier: t=0 -> 0, t=1 -> +1, t=2 -> -1
    int d = (t == 1) - (t == 2);
    out[idx] = x[idx + d * STRIDE];
}

extern "C" void kernel_launch(void* const* d_in, const int* in_sizes, int n_in,
                              void* d_out, int out_size) {
    const float* x = (const float*)d_in[0];   // [6561, 1] float32
    // d_in[1] is M [3,3] — permutation baked in.
    float* out = (float*)d_out;

    xd_gate_kernel<<<27, 243>>>(x, out);      // 27 * 243 = 6561 exactly
}

// round 7
// speedup vs baseline: 1.1384x; 1.1069x over previous
#include <cuda_runtime.h>

// XdGate on site INDEX=3 of an L=8 qutrit (D=3) state vector, N = 3^8 = 6561.
//
// U = I x I x I x M x I x I x I x I with M|i> = |(3-i) mod 3> — a pure
// permutation of the site-3 trit (stride 3^4 = 81):
//   t=0 -> delta 0, t=1 -> +81, t=2 -> -81 (element offsets).
//
// FINAL: launch-overhead bound. Evidence across 6 variants: ncu kernel time
// 3.97-4.54us with issue <=3-8% and DRAM 0.1%; harness graph-replay timing
// has +-0.6us noise on an IDENTICAL binary (R3 body: 5.02 vs 5.63us), so all
// body deltas are sub-noise. This variant combines the ncu-fastest body
// (trit from threadIdx only — valid because blockDim is a multiple of
// 3*STRIDE) with the minimal launch front: 9 blocks x 729 threads, exact
// cover of 6561, no bounds guard, no tail. 729 = 3^6 = 9*81, so
// t = (tid/81) % 3 with compile-time reciprocals.
// Vectorized 16B access impossible: src/dst offsets differ by 81 elements
// (4 bytes mod 16). Memcpy decompositions need >=3 graph nodes > 1 kernel.

static constexpr int STRIDE = 81;   // 3^4

__global__ __launch_bounds__(729) void xd_gate_kernel(
    const float* __restrict__ x, float* __restrict__ out) {
    int tid = threadIdx.x;                 // 0..728
    int t = (tid / STRIDE) % 3;            // site-3 trit (block base is mult. of 243)
    int d = (t == 1) - (t == 2);           // 0 -> 0, 1 -> +1, 2 -> -1
    int idx = blockIdx.x * 729 + tid;      // exact cover of [0, 6561)
    out[idx] = x[idx + d * STRIDE];
}

extern "C" void kernel_launch(void* const* d_in, const int* in_sizes, int n_in,
                              void* d_out, int out_size) {
    const float* x = (const float*)d_in[0];   // [6561, 1] float32
    // d_in[1] is M [3,3] — permutation baked in.
    float* out = (float*)d_out;

    xd_gate_kernel<<<9, 729>>>(x, out);       // 9 * 729 = 6561 exactly
}